// round 4
// baseline (speedup 1.0000x reference)
#include <cuda_runtime.h>

// Problem constants (fixed by the dataset).
#define NN 50000      // nodes
#define EE 800000     // edges
#define HH 128        // hidden / in channels
#define GG 64         // graphs
#define OO 8          // head out channels
#define NBLK_SCAN 196 // ceil(NN/256)

// ---------------- device scratch (no allocations allowed) ----------------
__device__ int   g_stride;           // 1 = indices are int32, 2 = int64 (read low words)
__device__ int   g_deg[NN];          // in-degree (excl self loop)
__device__ float g_dinv[NN];         // rsqrt(deg+1)
__device__ int   g_rowstart[NN];     // CSR row starts (by dst)
__device__ int   g_cursor[NN];
__device__ int   g_csrc[EE];         // CSR src node per slot
__device__ float g_coef[EE];         // dinv[src]*dinv[dst] per slot
__device__ int   g_bsum[NBLK_SCAN];
__device__ float g_t[(size_t)NN * HH];   // t = h @ W
__device__ float g_h[(size_t)NN * HH];   // layer output
__device__ float g_pool[GG * HH];
__device__ int   g_cnt[GG];

// ---------------- dtype detection ----------------
// If edge_index is int64, the odd int32 words (high words, values < 2^31) are
// all zero. If int32, they are random node ids and cannot all be zero.
__global__ void k_detect(const int* __restrict__ ei) {
    __shared__ int any;
    if (threadIdx.x == 0) any = 0;
    __syncthreads();
    int v = 0;
    for (int j = threadIdx.x; j < 2048; j += 256) v |= ei[2 * j + 1];
    if (v) atomicOr(&any, 1);
    __syncthreads();
    if (threadIdx.x == 0) g_stride = any ? 1 : 2;
}

__global__ void k_zero() {
    int i = blockIdx.x * 256 + threadIdx.x;
    if (i < NN) { g_deg[i] = 0; g_cursor[i] = 0; }
    if (i < GG * HH) g_pool[i] = 0.0f;
    if (i < GG) g_cnt[i] = 0;
}

__global__ void k_hist(const int* __restrict__ ei) {
    int e = blockIdx.x * 256 + threadIdx.x;
    if (e < EE) {
        int st = g_stride;
        int d = ei[(size_t)(EE + e) * st];
        atomicAdd(&g_deg[d], 1);
    }
}

__global__ void k_dinv() {
    int i = blockIdx.x * 256 + threadIdx.x;
    if (i < NN) g_dinv[i] = rsqrtf((float)g_deg[i] + 1.0f);
}

// Exclusive scan of g_deg into g_rowstart (3 kernels).
__global__ void k_scan1() {
    __shared__ int ws[8];
    int i = blockIdx.x * 256 + threadIdx.x;
    int v = (i < NN) ? g_deg[i] : 0;
    int lane = threadIdx.x & 31, w = threadIdx.x >> 5;
    int x = v;
    #pragma unroll
    for (int o = 1; o < 32; o <<= 1) {
        int y = __shfl_up_sync(0xFFFFFFFFu, x, o);
        if (lane >= o) x += y;
    }
    if (lane == 31) ws[w] = x;
    __syncthreads();
    if (threadIdx.x == 0) {
        int s = 0;
        #pragma unroll
        for (int k = 0; k < 8; k++) { int t = ws[k]; ws[k] = s; s += t; }
    }
    __syncthreads();
    x += ws[w];
    if (i < NN) g_rowstart[i] = x;                  // inclusive within block
    if (threadIdx.x == 255) g_bsum[blockIdx.x] = x; // block total
}

__global__ void k_scan2() {
    // tiny serial exclusive scan over 196 partials
    int s = 0;
    for (int b = 0; b < NBLK_SCAN; b++) { int t = g_bsum[b]; g_bsum[b] = s; s += t; }
}

__global__ void k_scan3() {
    int i = blockIdx.x * 256 + threadIdx.x;
    if (i < NN) g_rowstart[i] += g_bsum[blockIdx.x] - g_deg[i]; // -> exclusive
}

__global__ void k_fill(const int* __restrict__ ei) {
    int e = blockIdx.x * 256 + threadIdx.x;
    if (e < EE) {
        int st = g_stride;
        int s = ei[(size_t)e * st];
        int d = ei[(size_t)(EE + e) * st];
        int pos = g_rowstart[d] + atomicAdd(&g_cursor[d], 1);
        g_csrc[pos] = s;
        g_coef[pos] = g_dinv[s] * g_dinv[d];
    }
}

// ---------------- SGEMM: C[N,128] = A[N,128] @ W[128,128] ----------------
// 128x128 output tile per block, 256 threads, 8x8 register micro-tile.
__global__ __launch_bounds__(256) void k_gemm(const float* __restrict__ A,
                                              const float* __restrict__ W,
                                              float* __restrict__ C) {
    __shared__ float As[128 * 16];
    __shared__ float Bs[16 * 128];
    int tid = threadIdx.x;
    int tx = tid & 15, ty = tid >> 4;
    int rowbase = blockIdx.x * 128;

    float acc[8][8];
    #pragma unroll
    for (int i = 0; i < 8; i++)
        #pragma unroll
        for (int j = 0; j < 8; j++) acc[i][j] = 0.0f;

    for (int k0 = 0; k0 < 128; k0 += 16) {
        #pragma unroll
        for (int v = 0; v < 2; v++) {
            int idx = tid + v * 256;          // 0..511 float4 slots
            int ar = idx >> 2;                // 0..127
            int ac = (idx & 3) * 4;           // 0..12
            int r = rowbase + ar;
            float4 val = make_float4(0.f, 0.f, 0.f, 0.f);
            if (r < NN) val = *(const float4*)&A[(size_t)r * 128 + k0 + ac];
            *(float4*)&As[ar * 16 + ac] = val;
        }
        #pragma unroll
        for (int v = 0; v < 2; v++) {
            int idx = tid + v * 256;
            int br = idx >> 5;                // 0..15
            int bc = (idx & 31) * 4;          // 0..124
            *(float4*)&Bs[br * 128 + bc] = *(const float4*)&W[(size_t)(k0 + br) * 128 + bc];
        }
        __syncthreads();
        #pragma unroll
        for (int k = 0; k < 16; k++) {
            float a[8];
            #pragma unroll
            for (int i = 0; i < 8; i++) a[i] = As[(ty * 8 + i) * 16 + k];
            float4 b0 = *(float4*)&Bs[k * 128 + tx * 4];
            float4 b1 = *(float4*)&Bs[k * 128 + 64 + tx * 4];
            float b[8] = {b0.x, b0.y, b0.z, b0.w, b1.x, b1.y, b1.z, b1.w};
            #pragma unroll
            for (int i = 0; i < 8; i++)
                #pragma unroll
                for (int j = 0; j < 8; j++) acc[i][j] += a[i] * b[j];
        }
        __syncthreads();
    }
    #pragma unroll
    for (int i = 0; i < 8; i++) {
        int r = rowbase + ty * 8 + i;
        if (r < NN) {
            *(float4*)&C[(size_t)r * 128 + tx * 4] =
                make_float4(acc[i][0], acc[i][1], acc[i][2], acc[i][3]);
            *(float4*)&C[(size_t)r * 128 + 64 + tx * 4] =
                make_float4(acc[i][4], acc[i][5], acc[i][6], acc[i][7]);
        }
    }
}

// ---------------- atomic-free gather (one warp per node) ----------------
// out[i] = sum_{e in CSR(i)} coef[e]*t[src[e]] + dinv[i]^2 * t[i] + b   (opt relu)
template <bool RELU>
__global__ __launch_bounds__(128) void k_gather(const float* __restrict__ bias) {
    int warp = threadIdx.x >> 5;
    int lane = threadIdx.x & 31;
    int node = blockIdx.x * 4 + warp;
    if (node >= NN) return;
    int rs = g_rowstart[node];
    int d = g_deg[node];
    int c4 = lane * 4;

    float4 acc = make_float4(0.f, 0.f, 0.f, 0.f);
    int e = rs, end = rs + d;
    for (; e + 1 < end; e += 2) {
        int s0 = g_csrc[e], s1 = g_csrc[e + 1];
        float c0 = g_coef[e], c1 = g_coef[e + 1];
        float4 v0 = *(const float4*)&g_t[(size_t)s0 * 128 + c4];
        float4 v1 = *(const float4*)&g_t[(size_t)s1 * 128 + c4];
        acc.x += c0 * v0.x + c1 * v1.x;
        acc.y += c0 * v0.y + c1 * v1.y;
        acc.z += c0 * v0.z + c1 * v1.z;
        acc.w += c0 * v0.w + c1 * v1.w;
    }
    if (e < end) {
        int s0 = g_csrc[e];
        float c0 = g_coef[e];
        float4 v0 = *(const float4*)&g_t[(size_t)s0 * 128 + c4];
        acc.x += c0 * v0.x; acc.y += c0 * v0.y;
        acc.z += c0 * v0.z; acc.w += c0 * v0.w;
    }
    float di = g_dinv[node];
    float s2 = di * di;
    float4 tv = *(const float4*)&g_t[(size_t)node * 128 + c4];
    float4 bv = *(const float4*)&bias[c4];
    acc.x += s2 * tv.x + bv.x;
    acc.y += s2 * tv.y + bv.y;
    acc.z += s2 * tv.z + bv.z;
    acc.w += s2 * tv.w + bv.w;
    if (RELU) {
        acc.x = fmaxf(acc.x, 0.f); acc.y = fmaxf(acc.y, 0.f);
        acc.z = fmaxf(acc.z, 0.f); acc.w = fmaxf(acc.w, 0.f);
    }
    *(float4*)&g_h[(size_t)node * 128 + c4] = acc;
}

// ---------------- pooling (batch is sorted) ----------------
__global__ __launch_bounds__(128) void k_pool(const int* __restrict__ batch) {
    int c = threadIdx.x;                 // channel
    int start = blockIdx.x * 512;
    int end = min(start + 512, NN);
    if (start >= NN) return;
    int st = g_stride;
    float acc = 0.0f;
    int cur = batch[(size_t)start * st];
    for (int i = start; i < end; i++) {
        int b = batch[(size_t)i * st];
        if (b != cur) {
            atomicAdd(&g_pool[cur * HH + c], acc);
            acc = 0.0f;
            cur = b;
        }
        acc += g_h[(size_t)i * HH + c];
    }
    atomicAdd(&g_pool[cur * HH + c], acc);
}

__global__ void k_cnt(const int* __restrict__ batch) {
    __shared__ int sh[GG];
    if (threadIdx.x < GG) sh[threadIdx.x] = 0;
    __syncthreads();
    int i = blockIdx.x * 256 + threadIdx.x;
    if (i < NN) {
        int st = g_stride;
        atomicAdd(&sh[batch[(size_t)i * st]], 1);
    }
    __syncthreads();
    if (threadIdx.x < GG && sh[threadIdx.x]) atomicAdd(&g_cnt[threadIdx.x], sh[threadIdx.x]);
}

__global__ void k_head(const float* __restrict__ Wh, const float* __restrict__ bh,
                       float* __restrict__ out) {
    int tid = threadIdx.x;
    if (tid >= GG * OO) return;
    int g = tid >> 3, o = tid & 7;
    float cnt = fmaxf((float)g_cnt[g], 1.0f);
    float s = 0.0f;
    #pragma unroll
    for (int k = 0; k < HH; k++) s += g_pool[g * HH + k] * Wh[k * OO + o];
    out[g * OO + o] = s / cnt + bh[o];
}

// ---------------- driver ----------------
extern "C" void kernel_launch(void* const* d_in, const int* in_sizes, int n_in,
                              void* d_out, int out_size) {
    const float* x  = (const float*)d_in[0];
    const int*   ei = (const int*)d_in[1];
    const int*   bt = (const int*)d_in[2];
    const float* W0 = (const float*)d_in[3];
    const float* b0 = (const float*)d_in[4];
    const float* W1 = (const float*)d_in[5];
    const float* b1 = (const float*)d_in[6];
    const float* W2 = (const float*)d_in[7];
    const float* b2 = (const float*)d_in[8];
    const float* Wh = (const float*)d_in[9];
    const float* bh = (const float*)d_in[10];
    float* out = (float*)d_out;

    float *pt = nullptr, *ph = nullptr;
    cudaGetSymbolAddress((void**)&pt, g_t);
    cudaGetSymbolAddress((void**)&ph, g_h);

    k_detect<<<1, 256>>>(ei);
    k_zero<<<NBLK_SCAN, 256>>>();
    k_hist<<<(EE + 255) / 256, 256>>>(ei);
    k_dinv<<<NBLK_SCAN, 256>>>();
    k_scan1<<<NBLK_SCAN, 256>>>();
    k_scan2<<<1, 1>>>();
    k_scan3<<<NBLK_SCAN, 256>>>();
    k_fill<<<(EE + 255) / 256, 256>>>(ei);

    const int gemm_blocks = (NN + 127) / 128;  // 391
    const int gat_blocks  = (NN + 3) / 4;      // 12500

    // layer 0
    k_gemm<<<gemm_blocks, 256>>>(x, W0, pt);
    k_gather<true><<<gat_blocks, 128>>>(b0);
    // layer 1
    k_gemm<<<gemm_blocks, 256>>>(ph, W1, pt);
    k_gather<true><<<gat_blocks, 128>>>(b1);
    // layer 2 (no relu)
    k_gemm<<<gemm_blocks, 256>>>(ph, W2, pt);
    k_gather<false><<<gat_blocks, 128>>>(b2);

    k_pool<<<(NN + 511) / 512, 128>>>(bt);
    k_cnt<<<NBLK_SCAN, 256>>>(bt);
    k_head<<<1, 512>>>(Wh, bh, out);
}

// round 7
// speedup vs baseline: 1.1157x; 1.1157x over previous
#include <cuda_runtime.h>

// Problem constants (fixed by the dataset).
#define NN 50000      // nodes
#define EE 800000     // edges
#define HH 128        // hidden / in channels
#define GG 64         // graphs
#define OO 8          // head out channels
#define NBLK_SCAN 196 // ceil(NN/256)

// ---------------- device scratch (no allocations allowed) ----------------
__device__ int   g_stride;           // 1 = indices are int32, 2 = int64 (read low words)
__device__ int   g_deg[NN];          // in-degree (excl self loop)
__device__ float g_dinv[NN];         // rsqrt(deg+1)
__device__ int   g_rowstart[NN];     // CSR row starts (by dst)
__device__ int   g_cursor[NN];
__device__ int   g_csrc[EE];         // CSR src node per slot
__device__ float g_coef[EE];         // dinv[src]*dinv[dst] per slot
__device__ int   g_bsum[NBLK_SCAN];
__device__ float g_t[(size_t)NN * HH];   // t = h @ W
__device__ float g_h[(size_t)NN * HH];   // layer output
__device__ float g_pool[GG * HH];
__device__ int   g_cnt[GG];

// packed fp32x2 FMA (FFMA2) — only reachable via explicit PTX
__device__ __forceinline__ unsigned long long ffma2(unsigned long long a,
                                                    unsigned long long b,
                                                    unsigned long long c) {
    unsigned long long d;
    asm("fma.rn.f32x2 %0, %1, %2, %3;" : "=l"(d) : "l"(a), "l"(b), "l"(c));
    return d;
}

// ---------------- dtype detection ----------------
__global__ void k_detect(const int* __restrict__ ei) {
    __shared__ int any;
    if (threadIdx.x == 0) any = 0;
    __syncthreads();
    int v = 0;
    for (int j = threadIdx.x; j < 2048; j += 256) v |= ei[2 * j + 1];
    if (v) atomicOr(&any, 1);
    __syncthreads();
    if (threadIdx.x == 0) g_stride = any ? 1 : 2;
}

__global__ void k_zero() {
    int i = blockIdx.x * 256 + threadIdx.x;
    if (i < NN) { g_deg[i] = 0; g_cursor[i] = 0; }
    if (i < GG * HH) g_pool[i] = 0.0f;
    if (i < GG) g_cnt[i] = 0;
}

__global__ void k_hist(const int* __restrict__ ei) {
    int e = blockIdx.x * 256 + threadIdx.x;
    if (e < EE) {
        int st = g_stride;
        int d = ei[(size_t)(EE + e) * st];
        atomicAdd(&g_deg[d], 1);
    }
}

__global__ void k_dinv() {
    int i = blockIdx.x * 256 + threadIdx.x;
    if (i < NN) g_dinv[i] = rsqrtf((float)g_deg[i] + 1.0f);
}

// Exclusive scan of g_deg into g_rowstart (3 kernels).
__global__ void k_scan1() {
    __shared__ int ws[8];
    int i = blockIdx.x * 256 + threadIdx.x;
    int v = (i < NN) ? g_deg[i] : 0;
    int lane = threadIdx.x & 31, w = threadIdx.x >> 5;
    int x = v;
    #pragma unroll
    for (int o = 1; o < 32; o <<= 1) {
        int y = __shfl_up_sync(0xFFFFFFFFu, x, o);
        if (lane >= o) x += y;
    }
    if (lane == 31) ws[w] = x;
    __syncthreads();
    if (threadIdx.x == 0) {
        int s = 0;
        #pragma unroll
        for (int k = 0; k < 8; k++) { int t = ws[k]; ws[k] = s; s += t; }
    }
    __syncthreads();
    x += ws[w];
    if (i < NN) g_rowstart[i] = x;                  // inclusive within block
    if (threadIdx.x == 255) g_bsum[blockIdx.x] = x; // block total
}

// parallel exclusive scan over the 196 block partials (one 256-thread block)
__global__ void k_scan2() {
    __shared__ int ws[8];
    int i = threadIdx.x;
    int v = (i < NBLK_SCAN) ? g_bsum[i] : 0;
    int lane = i & 31, w = i >> 5;
    int x = v;
    #pragma unroll
    for (int o = 1; o < 32; o <<= 1) {
        int y = __shfl_up_sync(0xFFFFFFFFu, x, o);
        if (lane >= o) x += y;
    }
    if (lane == 31) ws[w] = x;
    __syncthreads();
    if (i == 0) {
        int s = 0;
        #pragma unroll
        for (int k = 0; k < 8; k++) { int t = ws[k]; ws[k] = s; s += t; }
    }
    __syncthreads();
    x += ws[w];
    if (i < NBLK_SCAN) g_bsum[i] = x - v;           // exclusive
}

__global__ void k_scan3() {
    int i = blockIdx.x * 256 + threadIdx.x;
    if (i < NN) g_rowstart[i] += g_bsum[blockIdx.x] - g_deg[i]; // -> exclusive
}

__global__ void k_fill(const int* __restrict__ ei) {
    int e = blockIdx.x * 256 + threadIdx.x;
    if (e < EE) {
        int st = g_stride;
        int s = ei[(size_t)e * st];
        int d = ei[(size_t)(EE + e) * st];
        int pos = g_rowstart[d] + atomicAdd(&g_cursor[d], 1);
        g_csrc[pos] = s;
        g_coef[pos] = g_dinv[s] * g_dinv[d];
    }
}

// ---------------- SGEMM: C[N,128] = A[N,128] @ W[128,128] ----------------
// 128x128 tile / block, 256 threads, 8x8 micro-tile computed as 8x4 FFMA2.
// A values are duplicated in SMEM ({a,a} pairs) so the mainloop needs zero
// pack MOVs: a-operand = 1 LDS.64 (warp-broadcast), b-operand pairs come
// straight out of the float4 load.
__global__ __launch_bounds__(256) void k_gemm(const float* __restrict__ A,
                                              const float* __restrict__ W,
                                              float* __restrict__ C) {
    __shared__ float As2[128 * 32];   // [row][2k] duplicated pairs, 16 KB
    __shared__ float Bs[16 * 128];    // [k][col], 8 KB
    int tid = threadIdx.x;
    int tx = tid & 15, ty = tid >> 4;
    int rowbase = blockIdx.x * 128;

    unsigned long long acc2[8][4];
    #pragma unroll
    for (int i = 0; i < 8; i++)
        #pragma unroll
        for (int j = 0; j < 4; j++) acc2[i][j] = 0ull;

    for (int k0 = 0; k0 < 128; k0 += 16) {
        // A tile -> duplicated pairs. 512 float4 slots, coalesced, no conflicts.
        #pragma unroll
        for (int v = 0; v < 2; v++) {
            int idx = tid + v * 256;
            int ar = idx >> 2;                // 0..127 row
            int ac = (idx & 3) * 4;           // k offset 0,4,8,12
            int r = rowbase + ar;
            float4 val = make_float4(0.f, 0.f, 0.f, 0.f);
            if (r < NN) val = *(const float4*)&A[(size_t)r * 128 + k0 + ac];
            float* dst = &As2[ar * 32 + ac * 2];
            *(float4*)(dst)     = make_float4(val.x, val.x, val.y, val.y);
            *(float4*)(dst + 4) = make_float4(val.z, val.z, val.w, val.w);
        }
        #pragma unroll
        for (int v = 0; v < 2; v++) {
            int idx = tid + v * 256;
            int br = idx >> 5;                // 0..15
            int bc = (idx & 31) * 4;          // 0..124
            *(float4*)&Bs[br * 128 + bc] = *(const float4*)&W[(size_t)(k0 + br) * 128 + bc];
        }
        __syncthreads();
        #pragma unroll
        for (int k = 0; k < 16; k++) {
            ulonglong2 bb0 = *(const ulonglong2*)&Bs[k * 128 + tx * 4];
            ulonglong2 bb1 = *(const ulonglong2*)&Bs[k * 128 + 64 + tx * 4];
            #pragma unroll
            for (int i = 0; i < 8; i++) {
                unsigned long long a2 =
                    *(const unsigned long long*)&As2[(ty * 8 + i) * 32 + k * 2];
                acc2[i][0] = ffma2(a2, bb0.x, acc2[i][0]);
                acc2[i][1] = ffma2(a2, bb0.y, acc2[i][1]);
                acc2[i][2] = ffma2(a2, bb1.x, acc2[i][2]);
                acc2[i][3] = ffma2(a2, bb1.y, acc2[i][3]);
            }
        }
        __syncthreads();
    }
    #pragma unroll
    for (int i = 0; i < 8; i++) {
        int r = rowbase + ty * 8 + i;
        if (r < NN) {
            ulonglong2 o0; o0.x = acc2[i][0]; o0.y = acc2[i][1];
            ulonglong2 o1; o1.x = acc2[i][2]; o1.y = acc2[i][3];
            *(ulonglong2*)&C[(size_t)r * 128 + tx * 4] = o0;
            *(ulonglong2*)&C[(size_t)r * 128 + 64 + tx * 4] = o1;
        }
    }
}

// ---------------- atomic-free gather (one warp per node) ----------------
template <bool RELU>
__global__ __launch_bounds__(128) void k_gather(const float* __restrict__ bias) {
    int warp = threadIdx.x >> 5;
    int lane = threadIdx.x & 31;
    int node = blockIdx.x * 4 + warp;
    if (node >= NN) return;
    int rs = g_rowstart[node];
    int d = g_deg[node];
    int c4 = lane * 4;

    float4 acc = make_float4(0.f, 0.f, 0.f, 0.f);
    int e = rs, end = rs + d;
    for (; e + 3 < end; e += 4) {
        int s0 = g_csrc[e],      s1 = g_csrc[e + 1];
        int s2i = g_csrc[e + 2], s3 = g_csrc[e + 3];
        float c0 = g_coef[e],     c1 = g_coef[e + 1];
        float c2 = g_coef[e + 2], c3 = g_coef[e + 3];
        float4 v0 = *(const float4*)&g_t[(size_t)s0 * 128 + c4];
        float4 v1 = *(const float4*)&g_t[(size_t)s1 * 128 + c4];
        float4 v2 = *(const float4*)&g_t[(size_t)s2i * 128 + c4];
        float4 v3 = *(const float4*)&g_t[(size_t)s3 * 128 + c4];
        acc.x += c0 * v0.x + c1 * v1.x + c2 * v2.x + c3 * v3.x;
        acc.y += c0 * v0.y + c1 * v1.y + c2 * v2.y + c3 * v3.y;
        acc.z += c0 * v0.z + c1 * v1.z + c2 * v2.z + c3 * v3.z;
        acc.w += c0 * v0.w + c1 * v1.w + c2 * v2.w + c3 * v3.w;
    }
    for (; e < end; e++) {
        int s0 = g_csrc[e];
        float c0 = g_coef[e];
        float4 v0 = *(const float4*)&g_t[(size_t)s0 * 128 + c4];
        acc.x += c0 * v0.x; acc.y += c0 * v0.y;
        acc.z += c0 * v0.z; acc.w += c0 * v0.w;
    }
    float di = g_dinv[node];
    float s2 = di * di;
    float4 tv = *(const float4*)&g_t[(size_t)node * 128 + c4];
    float4 bv = *(const float4*)&bias[c4];
    acc.x += s2 * tv.x + bv.x;
    acc.y += s2 * tv.y + bv.y;
    acc.z += s2 * tv.z + bv.z;
    acc.w += s2 * tv.w + bv.w;
    if (RELU) {
        acc.x = fmaxf(acc.x, 0.f); acc.y = fmaxf(acc.y, 0.f);
        acc.z = fmaxf(acc.z, 0.f); acc.w = fmaxf(acc.w, 0.f);
    }
    *(float4*)&g_h[(size_t)node * 128 + c4] = acc;
}

// ---------------- pooling (batch is sorted) + fused counting ----------------
__global__ __launch_bounds__(128) void k_pool(const int* __restrict__ batch) {
    int c = threadIdx.x;                 // channel
    int start = blockIdx.x * 512;
    int end = min(start + 512, NN);
    if (start >= NN) return;
    int st = g_stride;
    float acc = 0.0f;
    int run = 0;
    int cur = batch[(size_t)start * st];
    for (int i = start; i < end; i++) {
        int b = batch[(size_t)i * st];
        if (b != cur) {
            atomicAdd(&g_pool[cur * HH + c], acc);
            if (c == 0) atomicAdd(&g_cnt[cur], run);
            acc = 0.0f; run = 0;
            cur = b;
        }
        acc += g_h[(size_t)i * HH + c];
        run++;
    }
    atomicAdd(&g_pool[cur * HH + c], acc);
    if (c == 0) atomicAdd(&g_cnt[cur], run);
}

__global__ void k_head(const float* __restrict__ Wh, const float* __restrict__ bh,
                       float* __restrict__ out) {
    int tid = threadIdx.x;
    if (tid >= GG * OO) return;
    int g = tid >> 3, o = tid & 7;
    float cnt = fmaxf((float)g_cnt[g], 1.0f);
    float s = 0.0f;
    #pragma unroll
    for (int k = 0; k < HH; k++) s += g_pool[g * HH + k] * Wh[k * OO + o];
    out[g * OO + o] = s / cnt + bh[o];
}

// ---------------- driver (single stream, graph-capture safe) ----------------
extern "C" void kernel_launch(void* const* d_in, const int* in_sizes, int n_in,
                              void* d_out, int out_size) {
    const float* x  = (const float*)d_in[0];
    const int*   ei = (const int*)d_in[1];
    const int*   bt = (const int*)d_in[2];
    const float* W0 = (const float*)d_in[3];
    const float* b0 = (const float*)d_in[4];
    const float* W1 = (const float*)d_in[5];
    const float* b1 = (const float*)d_in[6];
    const float* W2 = (const float*)d_in[7];
    const float* b2 = (const float*)d_in[8];
    const float* Wh = (const float*)d_in[9];
    const float* bh = (const float*)d_in[10];
    float* out = (float*)d_out;

    float *pt = nullptr, *ph = nullptr;
    cudaGetSymbolAddress((void**)&pt, g_t);
    cudaGetSymbolAddress((void**)&ph, g_h);

    const int gemm_blocks = (NN + 127) / 128;  // 391
    const int gat_blocks  = (NN + 3) / 4;      // 12500

    // CSR build chain
    k_detect<<<1, 256>>>(ei);
    k_zero<<<NBLK_SCAN, 256>>>();
    k_hist<<<(EE + 255) / 256, 256>>>(ei);
    k_dinv<<<NBLK_SCAN, 256>>>();
    k_scan1<<<NBLK_SCAN, 256>>>();
    k_scan2<<<1, 256>>>();
    k_scan3<<<NBLK_SCAN, 256>>>();
    k_fill<<<(EE + 255) / 256, 256>>>(ei);

    // layer 0
    k_gemm<<<gemm_blocks, 256>>>(x, W0, pt);
    k_gather<true><<<gat_blocks, 128>>>(b0);
    // layer 1
    k_gemm<<<gemm_blocks, 256>>>(ph, W1, pt);
    k_gather<true><<<gat_blocks, 128>>>(b1);
    // layer 2 (no relu)
    k_gemm<<<gemm_blocks, 256>>>(ph, W2, pt);
    k_gather<false><<<gat_blocks, 128>>>(b2);

    k_pool<<<(NN + 511) / 512, 128>>>(bt);
    k_head<<<1, 512>>>(Wh, bh, out);
}

// round 11
// speedup vs baseline: 1.2104x; 1.0849x over previous
#include <cuda_runtime.h>
#include <cuda_bf16.h>
#include <cstdint>

// Problem constants (fixed by the dataset).
#define NN 50000      // nodes
#define EE 800000     // edges
#define HH 128        // hidden / in channels
#define GG 64         // graphs
#define OO 8          // head out channels
#define NBLK_SCAN 196 // ceil(NN/256)
#define NPAD 50048    // 391 * 128, padded rows for MMA tiles
#define ASTRIDE 136   // SMEM row stride in bf16 (272 B) — ldmatrix conflict-free

// ---------------- device scratch (no allocations allowed) ----------------
__device__ int   g_stride;           // 1 = indices are int32, 2 = int64 (read low words)
__device__ int   g_deg[NN];          // in-degree (excl self loop)
__device__ float g_dinv[NN];         // rsqrt(deg+1)
__device__ int   g_rowstart[NN];     // CSR row starts (by dst)
__device__ int   g_cursor[NN];
__device__ int   g_csrc[EE];         // CSR src node per slot
__device__ float g_coef[EE];         // dinv[src]*dinv[dst] per slot
__device__ int   g_bsum[NBLK_SCAN];
__device__ float g_t[(size_t)NN * HH];   // t = h @ W (fp32, gather input)
__device__ float g_h[(size_t)NN * HH];   // final layer output (fp32, pool input)
__device__ float g_pool[GG * HH];
__device__ int   g_cnt[GG];
// bf16 split operands for the MMA GEMM (pad rows stay zero forever)
__device__ __nv_bfloat16 g_ahi[(size_t)NPAD * HH];
__device__ __nv_bfloat16 g_alo[(size_t)NPAD * HH];
__device__ __nv_bfloat16 g_wthi[HH * HH];   // Wt[n][k] = W[k][n], hi part
__device__ __nv_bfloat16 g_wtlo[HH * HH];   // lo part

// ---------------- PTX helpers (baseline ISA only; no 'a'-features) --------
__device__ __forceinline__ uint32_t smem_u32(const void* p) {
    uint32_t a;
    asm("{ .reg .u64 t; cvta.to.shared.u64 t, %1; cvt.u32.u64 %0, t; }"
        : "=r"(a) : "l"(p));
    return a;
}
__device__ __forceinline__ void ldsm4(uint32_t* r, uint32_t addr) {
    asm volatile("ldmatrix.sync.aligned.m8n8.x4.shared.b16 {%0,%1,%2,%3}, [%4];"
                 : "=r"(r[0]), "=r"(r[1]), "=r"(r[2]), "=r"(r[3]) : "r"(addr));
}
__device__ __forceinline__ void ldsm2(uint32_t* r, uint32_t addr) {
    asm volatile("ldmatrix.sync.aligned.m8n8.x2.shared.b16 {%0,%1}, [%2];"
                 : "=r"(r[0]), "=r"(r[1]) : "r"(addr));
}
__device__ __forceinline__ void mma16816(float* d, const uint32_t* a, const uint32_t* b) {
    asm volatile("mma.sync.aligned.m16n8k16.row.col.f32.bf16.bf16.f32 "
                 "{%0,%1,%2,%3}, {%4,%5,%6,%7}, {%8,%9}, {%0,%1,%2,%3};"
                 : "+f"(d[0]), "+f"(d[1]), "+f"(d[2]), "+f"(d[3])
                 : "r"(a[0]), "r"(a[1]), "r"(a[2]), "r"(a[3]),
                   "r"(b[0]), "r"(b[1]));
}

// ---------------- dtype detection ----------------
__global__ void k_detect(const int* __restrict__ ei) {
    __shared__ int any;
    if (threadIdx.x == 0) any = 0;
    __syncthreads();
    int v = 0;
    for (int j = threadIdx.x; j < 2048; j += 256) v |= ei[2 * j + 1];
    if (v) atomicOr(&any, 1);
    __syncthreads();
    if (threadIdx.x == 0) g_stride = any ? 1 : 2;
}

__global__ void k_zero() {
    int i = blockIdx.x * 256 + threadIdx.x;
    if (i < NN) { g_deg[i] = 0; g_cursor[i] = 0; }
    if (i < GG * HH) g_pool[i] = 0.0f;
    if (i < GG) g_cnt[i] = 0;
}

__global__ void k_hist(const int* __restrict__ ei) {
    int e = blockIdx.x * 256 + threadIdx.x;
    if (e < EE) {
        int st = g_stride;
        int d = ei[(size_t)(EE + e) * st];
        atomicAdd(&g_deg[d], 1);
    }
}

__global__ void k_dinv() {
    int i = blockIdx.x * 256 + threadIdx.x;
    if (i < NN) g_dinv[i] = rsqrtf((float)g_deg[i] + 1.0f);
}

__global__ void k_scan1() {
    __shared__ int ws[8];
    int i = blockIdx.x * 256 + threadIdx.x;
    int v = (i < NN) ? g_deg[i] : 0;
    int lane = threadIdx.x & 31, w = threadIdx.x >> 5;
    int x = v;
    #pragma unroll
    for (int o = 1; o < 32; o <<= 1) {
        int y = __shfl_up_sync(0xFFFFFFFFu, x, o);
        if (lane >= o) x += y;
    }
    if (lane == 31) ws[w] = x;
    __syncthreads();
    if (threadIdx.x == 0) {
        int s = 0;
        #pragma unroll
        for (int k = 0; k < 8; k++) { int t = ws[k]; ws[k] = s; s += t; }
    }
    __syncthreads();
    x += ws[w];
    if (i < NN) g_rowstart[i] = x;
    if (threadIdx.x == 255) g_bsum[blockIdx.x] = x;
}

__global__ void k_scan2() {
    __shared__ int ws[8];
    int i = threadIdx.x;
    int v = (i < NBLK_SCAN) ? g_bsum[i] : 0;
    int lane = i & 31, w = i >> 5;
    int x = v;
    #pragma unroll
    for (int o = 1; o < 32; o <<= 1) {
        int y = __shfl_up_sync(0xFFFFFFFFu, x, o);
        if (lane >= o) x += y;
    }
    if (lane == 31) ws[w] = x;
    __syncthreads();
    if (i == 0) {
        int s = 0;
        #pragma unroll
        for (int k = 0; k < 8; k++) { int t = ws[k]; ws[k] = s; s += t; }
    }
    __syncthreads();
    x += ws[w];
    if (i < NBLK_SCAN) g_bsum[i] = x - v;
}

__global__ void k_scan3() {
    int i = blockIdx.x * 256 + threadIdx.x;
    if (i < NN) g_rowstart[i] += g_bsum[blockIdx.x] - g_deg[i];
}

__global__ void k_fill(const int* __restrict__ ei) {
    int e = blockIdx.x * 256 + threadIdx.x;
    if (e < EE) {
        int st = g_stride;
        int s = ei[(size_t)e * st];
        int d = ei[(size_t)(EE + e) * st];
        int pos = g_rowstart[d] + atomicAdd(&g_cursor[d], 1);
        g_csrc[pos] = s;
        g_coef[pos] = g_dinv[s] * g_dinv[d];
    }
}

// ---------------- operand split kernels ----------------
// x (fp32) -> hi/lo bf16 split
__global__ void k_xsplit(const float* __restrict__ x) {
    int i = blockIdx.x * 256 + threadIdx.x;   // float4 index
    if (i >= NN * 32) return;
    float4 v = ((const float4*)x)[i];
    __nv_bfloat162 h0 = __floats2bfloat162_rn(v.x, v.y);
    __nv_bfloat162 h1 = __floats2bfloat162_rn(v.z, v.w);
    float lx = v.x - __bfloat162float(__low2bfloat16(h0));
    float ly = v.y - __bfloat162float(__high2bfloat16(h0));
    float lz = v.z - __bfloat162float(__low2bfloat16(h1));
    float lw = v.w - __bfloat162float(__high2bfloat16(h1));
    __nv_bfloat162 l0 = __floats2bfloat162_rn(lx, ly);
    __nv_bfloat162 l1 = __floats2bfloat162_rn(lz, lw);
    uint2 ph, pl;
    ph.x = *(uint32_t*)&h0; ph.y = *(uint32_t*)&h1;
    pl.x = *(uint32_t*)&l0; pl.y = *(uint32_t*)&l1;
    ((uint2*)g_ahi)[i] = ph;
    ((uint2*)g_alo)[i] = pl;
}

// W [k][n] fp32 -> Wt [n][k] hi/lo bf16
__global__ void k_wsplit(const float* __restrict__ W) {
    for (int idx = threadIdx.x; idx < HH * HH; idx += 256) {
        int n = idx >> 7, k = idx & 127;
        float w = W[k * HH + n];
        __nv_bfloat16 hi = __float2bfloat16_rn(w);
        __nv_bfloat16 lo = __float2bfloat16_rn(w - __bfloat162float(hi));
        g_wthi[idx] = hi;
        g_wtlo[idx] = lo;
    }
}

// ---------------- HMMA GEMM: g_t = (Ahi+Alo) @ (Wthi+Wtlo)^T ------------
// 128x128 tile / block, 8 warps, warp tile 32x64, mma.sync m16n8k16 bf16,
// fp32 accumulate, 3 passes (hh, hl, lh).
#define SM_BYTES (4 * 128 * ASTRIDE * 2)

__global__ __launch_bounds__(256) void k_mma(float* __restrict__ C) {
    extern __shared__ __nv_bfloat16 sm[];
    __nv_bfloat16* sAhi = sm;
    __nv_bfloat16* sAlo = sm + 128 * ASTRIDE;
    __nv_bfloat16* sBhi = sm + 2 * 128 * ASTRIDE;
    __nv_bfloat16* sBlo = sm + 3 * 128 * ASTRIDE;
    int tid = threadIdx.x;
    int rowbase = blockIdx.x * 128;

    // load tiles: 128 rows x 128 bf16, row stride ASTRIDE (=17 uint4)
    {
        const uint4* gAhi = (const uint4*)(g_ahi + (size_t)rowbase * HH);
        const uint4* gAlo = (const uint4*)(g_alo + (size_t)rowbase * HH);
        const uint4* gBhi = (const uint4*)g_wthi;
        const uint4* gBlo = (const uint4*)g_wtlo;
        #pragma unroll
        for (int v = 0; v < 8; v++) {
            int idx = tid + v * 256;            // 0..2047 (uint4 slots)
            int r = idx >> 4;
            int c = idx & 15;
            int soff = r * (ASTRIDE / 8) + c;   // ASTRIDE/8 = 17
            ((uint4*)sAhi)[soff] = gAhi[idx];
            ((uint4*)sAlo)[soff] = gAlo[idx];
            ((uint4*)sBhi)[soff] = gBhi[idx];
            ((uint4*)sBlo)[soff] = gBlo[idx];
        }
    }
    __syncthreads();

    int w = tid >> 5, lane = tid & 31;
    int mbase = (w & 3) * 32;
    int nbase = (w >> 2) * 64;

    uint32_t baseA[2] = { smem_u32(sAhi), smem_u32(sAlo) };
    uint32_t baseB[2] = { smem_u32(sBhi), smem_u32(sBlo) };

    // per-lane ldmatrix byte offsets
    // A x4: lane -> row (lane&15), half (lane>>4) selects k 0-7 / 8-15
    int aoff = ((lane & 15) * ASTRIDE + (lane >> 4) * 8) * 2;
    // B x2: lanes 0-15 used; lane -> n-row (l&7), half (l>>3) selects k half
    int l15 = lane & 15;
    int boff = ((l15 & 7) * ASTRIDE + (l15 >> 3) * 8) * 2;

    float acc[2][8][4];
    #pragma unroll
    for (int mi = 0; mi < 2; mi++)
        #pragma unroll
        for (int j = 0; j < 8; j++)
            #pragma unroll
            for (int q = 0; q < 4; q++) acc[mi][j][q] = 0.0f;

    #pragma unroll
    for (int pass = 0; pass < 3; pass++) {
        uint32_t aB = baseA[pass == 2 ? 1 : 0] + mbase * ASTRIDE * 2 + aoff;
        uint32_t bB = baseB[pass == 1 ? 1 : 0] + nbase * ASTRIDE * 2 + boff;
        #pragma unroll
        for (int k = 0; k < 8; k++) {
            int ko = k * 32;                    // 16 bf16 = 32 B
            uint32_t a0[4], a1[4];
            ldsm4(a0, aB + ko);
            ldsm4(a1, aB + 16 * ASTRIDE * 2 + ko);
            #pragma unroll
            for (int j = 0; j < 8; j++) {
                uint32_t b[2];
                ldsm2(b, bB + j * 8 * ASTRIDE * 2 + ko);
                mma16816(acc[0][j], a0, b);
                mma16816(acc[1][j], a1, b);
            }
        }
    }

    // epilogue: acc fragment -> C rows (guard pad rows)
    int r0base = rowbase + mbase + (lane >> 2);
    int cbase = nbase + (lane & 3) * 2;
    #pragma unroll
    for (int mi = 0; mi < 2; mi++) {
        int r0 = r0base + mi * 16;
        #pragma unroll
        for (int j = 0; j < 8; j++) {
            int col = cbase + j * 8;
            if (r0 < NN)
                *(float2*)&C[(size_t)r0 * HH + col] =
                    make_float2(acc[mi][j][0], acc[mi][j][1]);
            if (r0 + 8 < NN)
                *(float2*)&C[(size_t)(r0 + 8) * HH + col] =
                    make_float2(acc[mi][j][2], acc[mi][j][3]);
        }
    }
}

// ---------------- atomic-free gather (one warp per node) ----------------
// SPLIT: write bf16 hi/lo (next GEMM operand); else write fp32 g_h.
template <bool RELU, bool SPLIT>
__global__ __launch_bounds__(128) void k_gather(const float* __restrict__ bias) {
    int warp = threadIdx.x >> 5;
    int lane = threadIdx.x & 31;
    int node = blockIdx.x * 4 + warp;
    if (node >= NN) return;
    int rs = g_rowstart[node];
    int d = g_deg[node];
    int c4 = lane * 4;

    float4 acc = make_float4(0.f, 0.f, 0.f, 0.f);
    int e = rs, end = rs + d;
    for (; e + 3 < end; e += 4) {
        int s0 = g_csrc[e],      s1 = g_csrc[e + 1];
        int s2i = g_csrc[e + 2], s3 = g_csrc[e + 3];
        float c0 = g_coef[e],     c1 = g_coef[e + 1];
        float c2 = g_coef[e + 2], c3 = g_coef[e + 3];
        float4 v0 = *(const float4*)&g_t[(size_t)s0 * 128 + c4];
        float4 v1 = *(const float4*)&g_t[(size_t)s1 * 128 + c4];
        float4 v2 = *(const float4*)&g_t[(size_t)s2i * 128 + c4];
        float4 v3 = *(const float4*)&g_t[(size_t)s3 * 128 + c4];
        acc.x += c0 * v0.x + c1 * v1.x + c2 * v2.x + c3 * v3.x;
        acc.y += c0 * v0.y + c1 * v1.y + c2 * v2.y + c3 * v3.y;
        acc.z += c0 * v0.z + c1 * v1.z + c2 * v2.z + c3 * v3.z;
        acc.w += c0 * v0.w + c1 * v1.w + c2 * v2.w + c3 * v3.w;
    }
    for (; e < end; e++) {
        int s0 = g_csrc[e];
        float c0 = g_coef[e];
        float4 v0 = *(const float4*)&g_t[(size_t)s0 * 128 + c4];
        acc.x += c0 * v0.x; acc.y += c0 * v0.y;
        acc.z += c0 * v0.z; acc.w += c0 * v0.w;
    }
    float di = g_dinv[node];
    float s2 = di * di;
    float4 tv = *(const float4*)&g_t[(size_t)node * 128 + c4];
    float4 bv = *(const float4*)&bias[c4];
    acc.x += s2 * tv.x + bv.x;
    acc.y += s2 * tv.y + bv.y;
    acc.z += s2 * tv.z + bv.z;
    acc.w += s2 * tv.w + bv.w;
    if (RELU) {
        acc.x = fmaxf(acc.x, 0.f); acc.y = fmaxf(acc.y, 0.f);
        acc.z = fmaxf(acc.z, 0.f); acc.w = fmaxf(acc.w, 0.f);
    }
    if (SPLIT) {
        __nv_bfloat162 h0 = __floats2bfloat162_rn(acc.x, acc.y);
        __nv_bfloat162 h1 = __floats2bfloat162_rn(acc.z, acc.w);
        float lx = acc.x - __bfloat162float(__low2bfloat16(h0));
        float ly = acc.y - __bfloat162float(__high2bfloat16(h0));
        float lz = acc.z - __bfloat162float(__low2bfloat16(h1));
        float lw = acc.w - __bfloat162float(__high2bfloat16(h1));
        __nv_bfloat162 l0 = __floats2bfloat162_rn(lx, ly);
        __nv_bfloat162 l1 = __floats2bfloat162_rn(lz, lw);
        uint2 ph, pl;
        ph.x = *(uint32_t*)&h0; ph.y = *(uint32_t*)&h1;
        pl.x = *(uint32_t*)&l0; pl.y = *(uint32_t*)&l1;
        *(uint2*)&g_ahi[(size_t)node * 128 + c4] = ph;
        *(uint2*)&g_alo[(size_t)node * 128 + c4] = pl;
    } else {
        *(float4*)&g_h[(size_t)node * 128 + c4] = acc;
    }
}

// ---------------- pooling (batch is sorted) + fused counting ----------------
__global__ __launch_bounds__(128) void k_pool(const int* __restrict__ batch) {
    int c = threadIdx.x;
    int start = blockIdx.x * 512;
    int end = min(start + 512, NN);
    if (start >= NN) return;
    int st = g_stride;
    float acc = 0.0f;
    int run = 0;
    int cur = batch[(size_t)start * st];
    for (int i = start; i < end; i++) {
        int b = batch[(size_t)i * st];
        if (b != cur) {
            atomicAdd(&g_pool[cur * HH + c], acc);
            if (c == 0) atomicAdd(&g_cnt[cur], run);
            acc = 0.0f; run = 0;
            cur = b;
        }
        acc += g_h[(size_t)i * HH + c];
        run++;
    }
    atomicAdd(&g_pool[cur * HH + c], acc);
    if (c == 0) atomicAdd(&g_cnt[cur], run);
}

__global__ void k_head(const float* __restrict__ Wh, const float* __restrict__ bh,
                       float* __restrict__ out) {
    int tid = threadIdx.x;
    if (tid >= GG * OO) return;
    int g = tid >> 3, o = tid & 7;
    float cnt = fmaxf((float)g_cnt[g], 1.0f);
    float s = 0.0f;
    #pragma unroll
    for (int k = 0; k < HH; k++) s += g_pool[g * HH + k] * Wh[k * OO + o];
    out[g * OO + o] = s / cnt + bh[o];
}

// ---------------- driver (single stream, graph-capture safe) ----------------
extern "C" void kernel_launch(void* const* d_in, const int* in_sizes, int n_in,
                              void* d_out, int out_size) {
    const float* x  = (const float*)d_in[0];
    const int*   ei = (const int*)d_in[1];
    const int*   bt = (const int*)d_in[2];
    const float* W0 = (const float*)d_in[3];
    const float* b0 = (const float*)d_in[4];
    const float* W1 = (const float*)d_in[5];
    const float* b1 = (const float*)d_in[6];
    const float* W2 = (const float*)d_in[7];
    const float* b2 = (const float*)d_in[8];
    const float* Wh = (const float*)d_in[9];
    const float* bh = (const float*)d_in[10];
    float* out = (float*)d_out;

    float* pt = nullptr;
    cudaGetSymbolAddress((void**)&pt, g_t);

    cudaFuncSetAttribute(k_mma, cudaFuncAttributeMaxDynamicSharedMemorySize, SM_BYTES);

    const int mma_blocks = (NN + 127) / 128;   // 391
    const int gat_blocks = (NN + 3) / 4;       // 12500

    // CSR build chain
    k_detect<<<1, 256>>>(ei);
    k_zero<<<NBLK_SCAN, 256>>>();
    k_hist<<<(EE + 255) / 256, 256>>>(ei);
    k_dinv<<<NBLK_SCAN, 256>>>();
    k_scan1<<<NBLK_SCAN, 256>>>();
    k_scan2<<<1, 256>>>();
    k_scan3<<<NBLK_SCAN, 256>>>();
    k_fill<<<(EE + 255) / 256, 256>>>(ei);

    // layer 0
    k_xsplit<<<(NN * 32 + 255) / 256, 256>>>(x);
    k_wsplit<<<1, 256>>>(W0);
    k_mma<<<mma_blocks, 256, SM_BYTES>>>(pt);
    k_gather<true, true><<<gat_blocks, 128>>>(b0);
    // layer 1
    k_wsplit<<<1, 256>>>(W1);
    k_mma<<<mma_blocks, 256, SM_BYTES>>>(pt);
    k_gather<true, true><<<gat_blocks, 128>>>(b1);
    // layer 2 (no relu, fp32 out for pooling)
    k_wsplit<<<1, 256>>>(W2);
    k_mma<<<mma_blocks, 256, SM_BYTES>>>(pt);
    k_gather<false, false><<<gat_blocks, 128>>>(b2);

    k_pool<<<(NN + 511) / 512, 128>>>(bt);
    k_head<<<1, 512>>>(Wh, bh, out);
}

// round 12
// speedup vs baseline: 1.8695x; 1.5445x over previous
#include <cuda_runtime.h>
#include <cuda_bf16.h>
#include <cstdint>

// Problem constants (fixed by the dataset).
#define NN 50000      // nodes
#define EE 800000     // edges
#define HH 128        // hidden / in channels
#define GG 64         // graphs
#define OO 8          // head out channels
#define NBLK_SCAN 196 // ceil(NN/256)
#define NPAD 50048    // 391 * 128, padded rows for MMA tiles
#define ASTRIDE 136   // SMEM row stride in bf16 (272 B) — ldmatrix conflict-free
#define XBLK 6250     // blocks for x split in k_prep

// ---------------- device scratch (no allocations allowed) ----------------
__device__ int   g_stride;           // 1 = indices are int32, 2 = int64 (read low words)
__device__ int   g_deg[NN];          // in-degree (excl self loop)
__device__ float g_dinv[NN];         // rsqrt(deg+1)
__device__ int   g_rowstart[NN];     // CSR row starts (by dst)
__device__ int   g_cursor[NN];
__device__ int   g_csrc[EE];         // CSR src node per slot
__device__ float g_coef[EE];         // dinv[src]*dinv[dst] per slot
__device__ int   g_bsum[NBLK_SCAN];
__device__ float g_t[(size_t)NN * HH];   // t = h @ W (fp32, gather input)
__device__ float g_h[(size_t)NN * HH];   // final layer output (fp32, pool input)
__device__ float g_pool[GG * HH];
__device__ int   g_cnt[GG];
// bf16 split operands for the MMA GEMM (pad rows stay zero forever)
__device__ __nv_bfloat16 g_ahi[(size_t)NPAD * HH];
__device__ __nv_bfloat16 g_alo[(size_t)NPAD * HH];
__device__ __nv_bfloat16 g_wthi[3 * HH * HH];  // Wt[n][k] = W[k][n], hi, 3 layers
__device__ __nv_bfloat16 g_wtlo[3 * HH * HH];  // lo part

// ---------------- PTX helpers (baseline ISA only; no 'a'-features) --------
__device__ __forceinline__ uint32_t smem_u32(const void* p) {
    uint32_t a;
    asm("{ .reg .u64 t; cvta.to.shared.u64 t, %1; cvt.u32.u64 %0, t; }"
        : "=r"(a) : "l"(p));
    return a;
}
__device__ __forceinline__ void ldsm4(uint32_t* r, uint32_t addr) {
    asm volatile("ldmatrix.sync.aligned.m8n8.x4.shared.b16 {%0,%1,%2,%3}, [%4];"
                 : "=r"(r[0]), "=r"(r[1]), "=r"(r[2]), "=r"(r[3]) : "r"(addr));
}
__device__ __forceinline__ void ldsm2(uint32_t* r, uint32_t addr) {
    asm volatile("ldmatrix.sync.aligned.m8n8.x2.shared.b16 {%0,%1}, [%2];"
                 : "=r"(r[0]), "=r"(r[1]) : "r"(addr));
}
__device__ __forceinline__ void mma16816(float* d, const uint32_t* a, const uint32_t* b) {
    asm volatile("mma.sync.aligned.m16n8k16.row.col.f32.bf16.bf16.f32 "
                 "{%0,%1,%2,%3}, {%4,%5,%6,%7}, {%8,%9}, {%0,%1,%2,%3};"
                 : "+f"(d[0]), "+f"(d[1]), "+f"(d[2]), "+f"(d[3])
                 : "r"(a[0]), "r"(a[1]), "r"(a[2]), "r"(a[3]),
                   "r"(b[0]), "r"(b[1]));
}

// ---------------- init: zero counters + dtype detection (fused) -----------
__global__ void k_zero(const int* __restrict__ ei) {
    int i = blockIdx.x * 256 + threadIdx.x;
    if (i < NN) { g_deg[i] = 0; g_cursor[i] = 0; }
    if (i < GG * HH) g_pool[i] = 0.0f;
    if (i < GG) g_cnt[i] = 0;
    if (blockIdx.x == 0) {
        // int64 edge_index has all-zero high words; int32 random ids cannot.
        __shared__ int any;
        if (threadIdx.x == 0) any = 0;
        __syncthreads();
        int v = 0;
        for (int j = threadIdx.x; j < 2048; j += 256) v |= ei[2 * j + 1];
        if (v) atomicOr(&any, 1);
        __syncthreads();
        if (threadIdx.x == 0) g_stride = any ? 1 : 2;
    }
}

__global__ void k_hist(const int* __restrict__ ei) {
    int e = blockIdx.x * 256 + threadIdx.x;
    if (e < EE) {
        int st = g_stride;
        int d = ei[(size_t)(EE + e) * st];
        atomicAdd(&g_deg[d], 1);
    }
}

// Exclusive scan of g_deg into g_rowstart (3 kernels), dinv fused into scan1.
__global__ void k_scan1() {
    __shared__ int ws[8];
    int i = blockIdx.x * 256 + threadIdx.x;
    int v = (i < NN) ? g_deg[i] : 0;
    if (i < NN) g_dinv[i] = rsqrtf((float)v + 1.0f);
    int lane = threadIdx.x & 31, w = threadIdx.x >> 5;
    int x = v;
    #pragma unroll
    for (int o = 1; o < 32; o <<= 1) {
        int y = __shfl_up_sync(0xFFFFFFFFu, x, o);
        if (lane >= o) x += y;
    }
    if (lane == 31) ws[w] = x;
    __syncthreads();
    if (threadIdx.x == 0) {
        int s = 0;
        #pragma unroll
        for (int k = 0; k < 8; k++) { int t = ws[k]; ws[k] = s; s += t; }
    }
    __syncthreads();
    x += ws[w];
    if (i < NN) g_rowstart[i] = x;
    if (threadIdx.x == 255) g_bsum[blockIdx.x] = x;
}

__global__ void k_scan2() {
    __shared__ int ws[8];
    int i = threadIdx.x;
    int v = (i < NBLK_SCAN) ? g_bsum[i] : 0;
    int lane = i & 31, w = i >> 5;
    int x = v;
    #pragma unroll
    for (int o = 1; o < 32; o <<= 1) {
        int y = __shfl_up_sync(0xFFFFFFFFu, x, o);
        if (lane >= o) x += y;
    }
    if (lane == 31) ws[w] = x;
    __syncthreads();
    if (i == 0) {
        int s = 0;
        #pragma unroll
        for (int k = 0; k < 8; k++) { int t = ws[k]; ws[k] = s; s += t; }
    }
    __syncthreads();
    x += ws[w];
    if (i < NBLK_SCAN) g_bsum[i] = x - v;
}

__global__ void k_scan3() {
    int i = blockIdx.x * 256 + threadIdx.x;
    if (i < NN) g_rowstart[i] += g_bsum[blockIdx.x] - g_deg[i];
}

__global__ void k_fill(const int* __restrict__ ei) {
    int e = blockIdx.x * 256 + threadIdx.x;
    if (e < EE) {
        int st = g_stride;
        int s = ei[(size_t)e * st];
        int d = ei[(size_t)(EE + e) * st];
        int pos = g_rowstart[d] + atomicAdd(&g_cursor[d], 1);
        g_csrc[pos] = s;
        g_coef[pos] = g_dinv[s] * g_dinv[d];
    }
}

// ---------------- fused operand prep: x split + all 3 W splits -----------
__global__ void k_prep(const float* __restrict__ x, const float* __restrict__ W0,
                       const float* __restrict__ W1, const float* __restrict__ W2) {
    int b = blockIdx.x;
    if (b < XBLK) {
        int i = b * 256 + threadIdx.x;   // float4 index
        if (i >= NN * 32) return;
        float4 v = ((const float4*)x)[i];
        __nv_bfloat162 h0 = __floats2bfloat162_rn(v.x, v.y);
        __nv_bfloat162 h1 = __floats2bfloat162_rn(v.z, v.w);
        float lx = v.x - __bfloat162float(__low2bfloat16(h0));
        float ly = v.y - __bfloat162float(__high2bfloat16(h0));
        float lz = v.z - __bfloat162float(__low2bfloat16(h1));
        float lw = v.w - __bfloat162float(__high2bfloat16(h1));
        __nv_bfloat162 l0 = __floats2bfloat162_rn(lx, ly);
        __nv_bfloat162 l1 = __floats2bfloat162_rn(lz, lw);
        uint2 ph, pl;
        ph.x = *(uint32_t*)&h0; ph.y = *(uint32_t*)&h1;
        pl.x = *(uint32_t*)&l0; pl.y = *(uint32_t*)&l1;
        ((uint2*)g_ahi)[i] = ph;
        ((uint2*)g_alo)[i] = pl;
    } else {
        int layer = b - XBLK;            // 0..2
        const float* W = (layer == 0) ? W0 : (layer == 1) ? W1 : W2;
        __nv_bfloat16* dsthi = g_wthi + layer * HH * HH;
        __nv_bfloat16* dstlo = g_wtlo + layer * HH * HH;
        for (int idx = threadIdx.x; idx < HH * HH; idx += 256) {
            int n = idx >> 7, k = idx & 127;
            float w = W[k * HH + n];
            __nv_bfloat16 hi = __float2bfloat16_rn(w);
            __nv_bfloat16 lo = __float2bfloat16_rn(w - __bfloat162float(hi));
            dsthi[idx] = hi;
            dstlo[idx] = lo;
        }
    }
}

// ---------------- HMMA GEMM: g_t = (Ahi+Alo) @ (Wthi+Wtlo)^T ------------
// 128x128 tile / block, 8 warps, warp tile 32x64, mma.sync m16n8k16 bf16,
// fp32 accumulate, 3 passes (hh, hl, lh).
#define SM_BYTES (4 * 128 * ASTRIDE * 2)

__global__ __launch_bounds__(256) void k_mma(float* __restrict__ C,
                                             const __nv_bfloat16* __restrict__ Whi,
                                             const __nv_bfloat16* __restrict__ Wlo) {
    extern __shared__ __nv_bfloat16 sm[];
    __nv_bfloat16* sAhi = sm;
    __nv_bfloat16* sAlo = sm + 128 * ASTRIDE;
    __nv_bfloat16* sBhi = sm + 2 * 128 * ASTRIDE;
    __nv_bfloat16* sBlo = sm + 3 * 128 * ASTRIDE;
    int tid = threadIdx.x;
    int rowbase = blockIdx.x * 128;

    // load tiles: 128 rows x 128 bf16, row stride ASTRIDE (=17 uint4)
    {
        const uint4* gAhi = (const uint4*)(g_ahi + (size_t)rowbase * HH);
        const uint4* gAlo = (const uint4*)(g_alo + (size_t)rowbase * HH);
        const uint4* gBhi = (const uint4*)Whi;
        const uint4* gBlo = (const uint4*)Wlo;
        #pragma unroll
        for (int v = 0; v < 8; v++) {
            int idx = tid + v * 256;            // 0..2047 (uint4 slots)
            int r = idx >> 4;
            int c = idx & 15;
            int soff = r * (ASTRIDE / 8) + c;   // ASTRIDE/8 = 17
            ((uint4*)sAhi)[soff] = gAhi[idx];
            ((uint4*)sAlo)[soff] = gAlo[idx];
            ((uint4*)sBhi)[soff] = gBhi[idx];
            ((uint4*)sBlo)[soff] = gBlo[idx];
        }
    }
    __syncthreads();

    int w = tid >> 5, lane = tid & 31;
    int mbase = (w & 3) * 32;
    int nbase = (w >> 2) * 64;

    uint32_t baseA[2] = { smem_u32(sAhi), smem_u32(sAlo) };
    uint32_t baseB[2] = { smem_u32(sBhi), smem_u32(sBlo) };

    // per-lane ldmatrix byte offsets
    int aoff = ((lane & 15) * ASTRIDE + (lane >> 4) * 8) * 2;
    int l15 = lane & 15;
    int boff = ((l15 & 7) * ASTRIDE + (l15 >> 3) * 8) * 2;

    float acc[2][8][4];
    #pragma unroll
    for (int mi = 0; mi < 2; mi++)
        #pragma unroll
        for (int j = 0; j < 8; j++)
            #pragma unroll
            for (int q = 0; q < 4; q++) acc[mi][j][q] = 0.0f;

    #pragma unroll
    for (int pass = 0; pass < 3; pass++) {
        uint32_t aB = baseA[pass == 2 ? 1 : 0] + mbase * ASTRIDE * 2 + aoff;
        uint32_t bB = baseB[pass == 1 ? 1 : 0] + nbase * ASTRIDE * 2 + boff;
        #pragma unroll
        for (int k = 0; k < 8; k++) {
            int ko = k * 32;                    // 16 bf16 = 32 B
            uint32_t a0[4], a1[4];
            ldsm4(a0, aB + ko);
            ldsm4(a1, aB + 16 * ASTRIDE * 2 + ko);
            #pragma unroll
            for (int j = 0; j < 8; j++) {
                uint32_t b[2];
                ldsm2(b, bB + j * 8 * ASTRIDE * 2 + ko);
                mma16816(acc[0][j], a0, b);
                mma16816(acc[1][j], a1, b);
            }
        }
    }

    // epilogue: acc fragment -> C rows (guard pad rows)
    int r0base = rowbase + mbase + (lane >> 2);
    int cbase = nbase + (lane & 3) * 2;
    #pragma unroll
    for (int mi = 0; mi < 2; mi++) {
        int r0 = r0base + mi * 16;
        #pragma unroll
        for (int j = 0; j < 8; j++) {
            int col = cbase + j * 8;
            if (r0 < NN)
                *(float2*)&C[(size_t)r0 * HH + col] =
                    make_float2(acc[mi][j][0], acc[mi][j][1]);
            if (r0 + 8 < NN)
                *(float2*)&C[(size_t)(r0 + 8) * HH + col] =
                    make_float2(acc[mi][j][2], acc[mi][j][3]);
        }
    }
}

// ---------------- gather: warp-cooperative, shfl-broadcast indices -------
// Lanes coalesce-load up to 32 (src,coef) pairs, then broadcast via shfl;
// each lane keeps up to 32 independent 16B row-loads in flight.
// SPLIT: write bf16 hi/lo (next GEMM operand); else write fp32 g_h.
template <bool RELU, bool SPLIT>
__global__ __launch_bounds__(128) void k_gather(const float* __restrict__ bias) {
    int warp = threadIdx.x >> 5;
    int lane = threadIdx.x & 31;
    int node = blockIdx.x * 4 + warp;
    if (node >= NN) return;
    int rs = g_rowstart[node];
    int d = g_deg[node];
    int c4 = lane * 4;

    float4 acc = make_float4(0.f, 0.f, 0.f, 0.f);
    for (int base = 0; base < d; base += 32) {
        int cnt = min(32, d - base);
        int s = 0; float cf = 0.0f;
        if (lane < cnt) {
            s = g_csrc[rs + base + lane];
            cf = g_coef[rs + base + lane];
        }
        int j = 0;
        for (; j + 3 < cnt; j += 4) {
            int s0 = __shfl_sync(0xFFFFFFFFu, s, j);
            int s1 = __shfl_sync(0xFFFFFFFFu, s, j + 1);
            int s2i = __shfl_sync(0xFFFFFFFFu, s, j + 2);
            int s3 = __shfl_sync(0xFFFFFFFFu, s, j + 3);
            float c0 = __shfl_sync(0xFFFFFFFFu, cf, j);
            float c1 = __shfl_sync(0xFFFFFFFFu, cf, j + 1);
            float c2 = __shfl_sync(0xFFFFFFFFu, cf, j + 2);
            float c3 = __shfl_sync(0xFFFFFFFFu, cf, j + 3);
            float4 v0 = *(const float4*)&g_t[(size_t)s0 * 128 + c4];
            float4 v1 = *(const float4*)&g_t[(size_t)s1 * 128 + c4];
            float4 v2 = *(const float4*)&g_t[(size_t)s2i * 128 + c4];
            float4 v3 = *(const float4*)&g_t[(size_t)s3 * 128 + c4];
            acc.x += c0 * v0.x + c1 * v1.x + c2 * v2.x + c3 * v3.x;
            acc.y += c0 * v0.y + c1 * v1.y + c2 * v2.y + c3 * v3.y;
            acc.z += c0 * v0.z + c1 * v1.z + c2 * v2.z + c3 * v3.z;
            acc.w += c0 * v0.w + c1 * v1.w + c2 * v2.w + c3 * v3.w;
        }
        for (; j < cnt; j++) {
            int s0 = __shfl_sync(0xFFFFFFFFu, s, j);
            float c0 = __shfl_sync(0xFFFFFFFFu, cf, j);
            float4 v0 = *(const float4*)&g_t[(size_t)s0 * 128 + c4];
            acc.x += c0 * v0.x; acc.y += c0 * v0.y;
            acc.z += c0 * v0.z; acc.w += c0 * v0.w;
        }
    }
    float di = g_dinv[node];
    float s2 = di * di;
    float4 tv = *(const float4*)&g_t[(size_t)node * 128 + c4];
    float4 bv = *(const float4*)&bias[c4];
    acc.x += s2 * tv.x + bv.x;
    acc.y += s2 * tv.y + bv.y;
    acc.z += s2 * tv.z + bv.z;
    acc.w += s2 * tv.w + bv.w;
    if (RELU) {
        acc.x = fmaxf(acc.x, 0.f); acc.y = fmaxf(acc.y, 0.f);
        acc.z = fmaxf(acc.z, 0.f); acc.w = fmaxf(acc.w, 0.f);
    }
    if (SPLIT) {
        __nv_bfloat162 h0 = __floats2bfloat162_rn(acc.x, acc.y);
        __nv_bfloat162 h1 = __floats2bfloat162_rn(acc.z, acc.w);
        float lx = acc.x - __bfloat162float(__low2bfloat16(h0));
        float ly = acc.y - __bfloat162float(__high2bfloat16(h0));
        float lz = acc.z - __bfloat162float(__low2bfloat16(h1));
        float lw = acc.w - __bfloat162float(__high2bfloat16(h1));
        __nv_bfloat162 l0 = __floats2bfloat162_rn(lx, ly);
        __nv_bfloat162 l1 = __floats2bfloat162_rn(lz, lw);
        uint2 ph, pl;
        ph.x = *(uint32_t*)&h0; ph.y = *(uint32_t*)&h1;
        pl.x = *(uint32_t*)&l0; pl.y = *(uint32_t*)&l1;
        *(uint2*)&g_ahi[(size_t)node * 128 + c4] = ph;
        *(uint2*)&g_alo[(size_t)node * 128 + c4] = pl;
    } else {
        *(float4*)&g_h[(size_t)node * 128 + c4] = acc;
    }
}

// ---------------- pooling (batch is sorted) + fused counting -------------
// 64-row chunks -> 782 blocks for real occupancy (was 98 blocks).
#define POOL_CHUNK 64
__global__ __launch_bounds__(128) void k_pool(const int* __restrict__ batch) {
    int c = threadIdx.x;
    int start = blockIdx.x * POOL_CHUNK;
    int end = min(start + POOL_CHUNK, NN);
    if (start >= NN) return;
    int st = g_stride;
    float acc = 0.0f;
    int run = 0;
    int cur = batch[(size_t)start * st];
    for (int i = start; i < end; i++) {
        int b = batch[(size_t)i * st];
        if (b != cur) {
            atomicAdd(&g_pool[cur * HH + c], acc);
            if (c == 0) atomicAdd(&g_cnt[cur], run);
            acc = 0.0f; run = 0;
            cur = b;
        }
        acc += g_h[(size_t)i * HH + c];
        run++;
    }
    atomicAdd(&g_pool[cur * HH + c], acc);
    if (c == 0) atomicAdd(&g_cnt[cur], run);
}

__global__ void k_head(const float* __restrict__ Wh, const float* __restrict__ bh,
                       float* __restrict__ out) {
    int tid = threadIdx.x;
    if (tid >= GG * OO) return;
    int g = tid >> 3, o = tid & 7;
    float cnt = fmaxf((float)g_cnt[g], 1.0f);
    float s = 0.0f;
    #pragma unroll
    for (int k = 0; k < HH; k++) s += g_pool[g * HH + k] * Wh[k * OO + o];
    out[g * OO + o] = s / cnt + bh[o];
}

// ---------------- driver (single stream, graph-capture safe) ----------------
extern "C" void kernel_launch(void* const* d_in, const int* in_sizes, int n_in,
                              void* d_out, int out_size) {
    const float* x  = (const float*)d_in[0];
    const int*   ei = (const int*)d_in[1];
    const int*   bt = (const int*)d_in[2];
    const float* W0 = (const float*)d_in[3];
    const float* b0 = (const float*)d_in[4];
    const float* W1 = (const float*)d_in[5];
    const float* b1 = (const float*)d_in[6];
    const float* W2 = (const float*)d_in[7];
    const float* b2 = (const float*)d_in[8];
    const float* Wh = (const float*)d_in[9];
    const float* bh = (const float*)d_in[10];
    float* out = (float*)d_out;

    float* pt = nullptr;
    __nv_bfloat16 *pwhi = nullptr, *pwlo = nullptr;
    cudaGetSymbolAddress((void**)&pt, g_t);
    cudaGetSymbolAddress((void**)&pwhi, g_wthi);
    cudaGetSymbolAddress((void**)&pwlo, g_wtlo);

    cudaFuncSetAttribute(k_mma, cudaFuncAttributeMaxDynamicSharedMemorySize, SM_BYTES);

    const int mma_blocks  = (NN + 127) / 128;       // 391
    const int gat_blocks  = (NN + 3) / 4;           // 12500
    const int pool_blocks = (NN + POOL_CHUNK - 1) / POOL_CHUNK;  // 782

    // operand prep (x split + all 3 W splits) — independent of everything else
    k_prep<<<XBLK + 3, 256>>>(x, W0, W1, W2);

    // CSR build chain
    k_zero<<<NBLK_SCAN, 256>>>(ei);
    k_hist<<<(EE + 255) / 256, 256>>>(ei);
    k_scan1<<<NBLK_SCAN, 256>>>();
    k_scan2<<<1, 256>>>();
    k_scan3<<<NBLK_SCAN, 256>>>();
    k_fill<<<(EE + 255) / 256, 256>>>(ei);

    // layer 0
    k_mma<<<mma_blocks, 256, SM_BYTES>>>(pt, pwhi, pwlo);
    k_gather<true, true><<<gat_blocks, 128>>>(b0);
    // layer 1
    k_mma<<<mma_blocks, 256, SM_BYTES>>>(pt, pwhi + HH * HH, pwlo + HH * HH);
    k_gather<true, true><<<gat_blocks, 128>>>(b1);
    // layer 2 (no relu, fp32 out for pooling)
    k_mma<<<mma_blocks, 256, SM_BYTES>>>(pt, pwhi + 2 * HH * HH, pwlo + 2 * HH * HH);
    k_gather<false, false><<<gat_blocks, 128>>>(b2);

    k_pool<<<pool_blocks, 128>>>(bt);
    k_head<<<1, 512>>>(Wh, bh, out);
}